// round 4
// baseline (speedup 1.0000x reference)
#include <cuda_runtime.h>
#include <cstdint>

// Problem constants
#define NN 40000
#define EE 640000
#define DD 128
#define EDD 16
#define LL 3
#define BN_INV 0.99999500003749978f  // 1/sqrt(1+1e-5)

// Scratch (no cudaMalloc allowed)
__device__ float g_h[(size_t)NN * DD];
__device__ float g_h2[(size_t)NN * DD];
__device__ float g_agg[(size_t)NN * DD];
__device__ float g_t[(size_t)NN * 2 * DD];

// ---------------------------------------------------------------------------
// agg = (1+eps[l]) * h   (initializes the segment-sum accumulator)
// ---------------------------------------------------------------------------
__global__ void init_agg_kernel(const float* __restrict__ h,
                                const float* __restrict__ eps_l,
                                float* __restrict__ agg, int n4) {
    int i = blockIdx.x * blockDim.x + threadIdx.x;
    if (i >= n4) return;
    float s = 1.0f + eps_l[0];
    float4 v = ((const float4*)h)[i];
    v.x *= s; v.y *= s; v.z *= s; v.w *= s;
    ((float4*)agg)[i] = v;
}

// ---------------------------------------------------------------------------
// Fused edge kernel: one warp per edge (grid-strided).
//   e   = edge_attr[e] @ edge_W[l] + edge_b[l]        (register-resident W slice)
//   a   = sigmoid(xi . wA[0:128] + xj . wA[128:256] + attn_b)
//   msg = relu(xj * a + e)
//   agg[dst] += msg  (red.global.add.v4.f32)
// ---------------------------------------------------------------------------
__global__ __launch_bounds__(256)
void edge_kernel(const float* __restrict__ h,
                 const float* __restrict__ edge_attr,
                 const int* __restrict__ edge_index,
                 const float* __restrict__ edge_W,   // [16,128] (layer slice)
                 const float* __restrict__ edge_b,   // [128]
                 const float* __restrict__ attn_W,   // [256]
                 const float* __restrict__ attn_b,   // [1]
                 float* __restrict__ agg) {
    const int lane = threadIdx.x & 31;
    const int gw = (blockIdx.x * blockDim.x + threadIdx.x) >> 5;
    const int nwarp = (gridDim.x * blockDim.x) >> 5;
    const int d0 = lane * 4;

    // Per-lane weight slices held in registers across all edges of this warp.
    float4 wE[16];
#pragma unroll
    for (int k = 0; k < 16; k++)
        wE[k] = *(const float4*)(edge_W + k * DD + d0);
    const float4 wAi = *(const float4*)(attn_W + d0);
    const float4 wAj = *(const float4*)(attn_W + DD + d0);
    const float4 eb  = *(const float4*)(edge_b + d0);
    const float ab = attn_b[0];

    const int* __restrict__ src_arr = edge_index;
    const int* __restrict__ dst_arr = edge_index + EE;

    for (int e = gw; e < EE; e += nwarp) {
        const int s = src_arr[e];
        const int d = dst_arr[e];
        const float4 xj = *(const float4*)(h + (size_t)s * DD + d0);
        const float4 xi = *(const float4*)(h + (size_t)d * DD + d0);

        // attention logit: warp-wide dot product
        float p = xi.x * wAi.x + xi.y * wAi.y + xi.z * wAi.z + xi.w * wAi.w
                + xj.x * wAj.x + xj.y * wAj.y + xj.z * wAj.z + xj.w * wAj.w;
#pragma unroll
        for (int off = 16; off > 0; off >>= 1)
            p += __shfl_xor_sync(0xffffffffu, p, off);
        const float a = 1.0f / (1.0f + __expf(-(p + ab)));

        // edge_attr row (broadcast loads, 16 scalars)
        const float4* ea4 = (const float4*)(edge_attr + (size_t)e * EDD);
        float ea[16];
        {
            float4 t0 = ea4[0], t1 = ea4[1], t2 = ea4[2], t3 = ea4[3];
            ea[0]=t0.x; ea[1]=t0.y; ea[2]=t0.z; ea[3]=t0.w;
            ea[4]=t1.x; ea[5]=t1.y; ea[6]=t1.z; ea[7]=t1.w;
            ea[8]=t2.x; ea[9]=t2.y; ea[10]=t2.z; ea[11]=t2.w;
            ea[12]=t3.x; ea[13]=t3.y; ea[14]=t3.z; ea[15]=t3.w;
        }
        float4 ev = eb;
#pragma unroll
        for (int k = 0; k < 16; k++) {
            ev.x = fmaf(ea[k], wE[k].x, ev.x);
            ev.y = fmaf(ea[k], wE[k].y, ev.y);
            ev.z = fmaf(ea[k], wE[k].z, ev.z);
            ev.w = fmaf(ea[k], wE[k].w, ev.w);
        }
        float4 m;
        m.x = fmaxf(fmaf(xj.x, a, ev.x), 0.0f);
        m.y = fmaxf(fmaf(xj.y, a, ev.y), 0.0f);
        m.z = fmaxf(fmaf(xj.z, a, ev.z), 0.0f);
        m.w = fmaxf(fmaf(xj.w, a, ev.w), 0.0f);

        float* dstp = agg + (size_t)d * DD + d0;
        asm volatile("red.global.add.v4.f32 [%0], {%1,%2,%3,%4};"
                     :: "l"(dstp), "f"(m.x), "f"(m.y), "f"(m.z), "f"(m.w)
                     : "memory");
    }
}

// ---------------------------------------------------------------------------
// Generic SGEMM: C[M,Nc] = epi(A[M,K] @ B[K,Nc])
// epi: v += bias[c]; if bn: v = bn_g[c]*v*BN_INV + bn_b[c]; if relu: max(0,v)
// Block tile 128x128x8, 256 threads, 8x8 per thread.
// ---------------------------------------------------------------------------
__global__ __launch_bounds__(256)
void sgemm_kernel(const float* __restrict__ A, const float* __restrict__ B,
                  const float* __restrict__ bias,
                  const float* __restrict__ bn_g, const float* __restrict__ bn_b,
                  float* __restrict__ C,
                  int M, int K, int Nc, int do_relu, int do_bn) {
    __shared__ float As[8][128];
    __shared__ float Bs[8][128];

    const int tid = threadIdx.x;
    const int tx = tid & 15;        // 0..15  -> col group
    const int ty = tid >> 4;        // 0..15  -> row group
    const int row0 = blockIdx.y * 128;
    const int col0 = blockIdx.x * 128;

    const int a_row = tid >> 1;          // 0..127
    const int a_col = (tid & 1) * 4;     // 0 or 4
    const int b_row = tid >> 5;          // 0..7
    const int b_col = (tid & 31) * 4;    // 0..124

    float acc[8][8];
#pragma unroll
    for (int i = 0; i < 8; i++)
#pragma unroll
        for (int j = 0; j < 8; j++) acc[i][j] = 0.0f;

    for (int k0 = 0; k0 < K; k0 += 8) {
        float4 av = make_float4(0.f, 0.f, 0.f, 0.f);
        const int gr = row0 + a_row;
        if (gr < M) av = *(const float4*)(A + (size_t)gr * K + k0 + a_col);
        As[a_col + 0][a_row] = av.x;
        As[a_col + 1][a_row] = av.y;
        As[a_col + 2][a_row] = av.z;
        As[a_col + 3][a_row] = av.w;
        const float4 bv = *(const float4*)(B + (size_t)(k0 + b_row) * Nc + col0 + b_col);
        *(float4*)&Bs[b_row][b_col] = bv;
        __syncthreads();
#pragma unroll
        for (int k = 0; k < 8; k++) {
            float af[8], bf[8];
            *(float4*)&af[0] = *(const float4*)&As[k][ty * 8];
            *(float4*)&af[4] = *(const float4*)&As[k][ty * 8 + 4];
            *(float4*)&bf[0] = *(const float4*)&Bs[k][tx * 8];
            *(float4*)&bf[4] = *(const float4*)&Bs[k][tx * 8 + 4];
#pragma unroll
            for (int i = 0; i < 8; i++)
#pragma unroll
                for (int j = 0; j < 8; j++)
                    acc[i][j] = fmaf(af[i], bf[j], acc[i][j]);
        }
        __syncthreads();
    }

    // epilogue
    float bi[8], g[8], bb[8];
#pragma unroll
    for (int j = 0; j < 8; j++) {
        const int c = col0 + tx * 8 + j;
        bi[j] = bias[c];
        if (do_bn) { g[j] = bn_g[c]; bb[j] = bn_b[c]; }
    }
#pragma unroll
    for (int i = 0; i < 8; i++) {
        const int r = row0 + ty * 8 + i;
        if (r >= M) continue;
        float v[8];
#pragma unroll
        for (int j = 0; j < 8; j++) {
            float t = acc[i][j] + bi[j];
            if (do_bn) t = fmaf(g[j] * BN_INV, t, bb[j]);
            if (do_relu) t = fmaxf(t, 0.0f);
            v[j] = t;
        }
        float* cp = C + (size_t)r * Nc + col0 + tx * 8;
        *(float4*)cp       = make_float4(v[0], v[1], v[2], v[3]);
        *(float4*)(cp + 4) = make_float4(v[4], v[5], v[6], v[7]);
    }
}

// ---------------------------------------------------------------------------
extern "C" void kernel_launch(void* const* d_in, const int* in_sizes, int n_in,
                              void* d_out, int out_size) {
    const float* x         = (const float*)d_in[0];
    const float* edge_attr = (const float*)d_in[1];
    const float* node_W    = (const float*)d_in[2];
    const float* node_b    = (const float*)d_in[3];
    const float* edge_W    = (const float*)d_in[4];
    const float* edge_b    = (const float*)d_in[5];
    const float* attn_W    = (const float*)d_in[6];
    const float* attn_b    = (const float*)d_in[7];
    const float* eps       = (const float*)d_in[8];
    const float* W1        = (const float*)d_in[9];
    const float* b1        = (const float*)d_in[10];
    const float* bn1_g     = (const float*)d_in[11];
    const float* bn1_b     = (const float*)d_in[12];
    const float* W2        = (const float*)d_in[13];
    const float* b2        = (const float*)d_in[14];
    const float* bn_g      = (const float*)d_in[15];
    const float* bn_b      = (const float*)d_in[16];
    const int*   edge_index= (const int*)d_in[17];

    float *hA, *hB, *agg, *tbuf;
    cudaGetSymbolAddress((void**)&hA,  g_h);
    cudaGetSymbolAddress((void**)&hB,  g_h2);
    cudaGetSymbolAddress((void**)&agg, g_agg);
    cudaGetSymbolAddress((void**)&tbuf, g_t);

    const int mblk = (NN + 127) / 128;     // 313
    const int n4 = NN * DD / 4;

    // node encoder: h = x @ node_W + node_b
    sgemm_kernel<<<dim3(1, mblk), 256>>>(x, node_W, node_b, nullptr, nullptr,
                                         hA, NN, DD, DD, 0, 0);

    const float* hcur = hA;
    float* hnext = hB;
    for (int l = 0; l < LL; l++) {
        init_agg_kernel<<<(n4 + 255) / 256, 256>>>(hcur, eps + l, agg, n4);
        edge_kernel<<<2048, 256>>>(hcur, edge_attr, edge_index,
                                   edge_W + (size_t)l * EDD * DD,
                                   edge_b + (size_t)l * DD,
                                   attn_W + (size_t)l * 2 * DD,
                                   attn_b + l, agg);
        // t = relu(bn1(agg @ W1 + b1))   [N,128]@[128,256]
        sgemm_kernel<<<dim3(2, mblk), 256>>>(agg, W1 + (size_t)l * DD * 2 * DD,
                                             b1 + (size_t)l * 2 * DD,
                                             bn1_g + (size_t)l * 2 * DD,
                                             bn1_b + (size_t)l * 2 * DD,
                                             tbuf, NN, DD, 2 * DD, 1, 1);
        // h' = [relu] bn(t @ W2 + b2)    [N,256]@[256,128]
        float* outp = (l == LL - 1) ? (float*)d_out : hnext;
        sgemm_kernel<<<dim3(1, mblk), 256>>>(tbuf, W2 + (size_t)l * 2 * DD * DD,
                                             b2 + (size_t)l * DD,
                                             bn_g + (size_t)l * DD,
                                             bn_b + (size_t)l * DD,
                                             outp, NN, 2 * DD, DD, (l < LL - 1) ? 1 : 0, 1);
        if (l < LL - 1) {
            hcur = outp;
            hnext = (outp == hA) ? hB : hA;
        }
    }
}

// round 5
// speedup vs baseline: 1.7656x; 1.7656x over previous
#include <cuda_runtime.h>
#include <cstdint>

// Problem constants
#define NN 40000
#define EE 640000
#define DD 128
#define EDD 16
#define LL 3
#define BN_INV 0.99999500003749978f  // 1/sqrt(1+1e-5)

// Scratch (no cudaMalloc allowed)
__device__ float g_h[(size_t)NN * DD];
__device__ float g_h2[(size_t)NN * DD];
__device__ float g_agg[(size_t)NN * DD];
__device__ float g_t[(size_t)NN * 2 * DD];

// ---------------------------------------------------------------------------
// agg = (1+eps[l]) * h
// ---------------------------------------------------------------------------
__global__ void init_agg_kernel(const float* __restrict__ h,
                                const float* __restrict__ eps_l,
                                float* __restrict__ agg, int n4) {
    int i = blockIdx.x * blockDim.x + threadIdx.x;
    if (i >= n4) return;
    float s = 1.0f + eps_l[0];
    float4 v = ((const float4*)h)[i];
    v.x *= s; v.y *= s; v.z *= s; v.w *= s;
    ((float4*)agg)[i] = v;
}

// ---------------------------------------------------------------------------
// Fused edge kernel, 2 edges per warp iteration (ILP), 128-thread CTAs.
// ---------------------------------------------------------------------------
__global__ __launch_bounds__(128, 3)
void edge_kernel(const float* __restrict__ h,
                 const float* __restrict__ edge_attr,
                 const int* __restrict__ edge_index,
                 const float* __restrict__ edge_W,   // [16,128]
                 const float* __restrict__ edge_b,   // [128]
                 const float* __restrict__ attn_W,   // [256]
                 const float* __restrict__ attn_b,   // [1]
                 float* __restrict__ agg) {
    const int lane = threadIdx.x & 31;
    const int gw = (blockIdx.x * blockDim.x + threadIdx.x) >> 5;
    const int nwarp = (gridDim.x * blockDim.x) >> 5;
    const int d0 = lane * 4;

    float4 wE[16];
#pragma unroll
    for (int k = 0; k < 16; k++)
        wE[k] = *(const float4*)(edge_W + k * DD + d0);
    const float4 wAi = *(const float4*)(attn_W + d0);
    const float4 wAj = *(const float4*)(attn_W + DD + d0);
    const float4 eb  = *(const float4*)(edge_b + d0);
    const float ab = attn_b[0];

    const int* __restrict__ src_arr = edge_index;
    const int* __restrict__ dst_arr = edge_index + EE;

#pragma unroll 1
    for (int e0 = gw * 2; e0 < EE; e0 += nwarp * 2) {
        const int e1 = e0 + 1;   // EE even, e0 even -> always valid
        const int s0 = src_arr[e0], s1 = src_arr[e1];
        const int t0i = dst_arr[e0], t1i = dst_arr[e1];

        const float4 xj0 = *(const float4*)(h + (size_t)s0 * DD + d0);
        const float4 xi0 = *(const float4*)(h + (size_t)t0i * DD + d0);
        const float4 xj1 = *(const float4*)(h + (size_t)s1 * DD + d0);
        const float4 xi1 = *(const float4*)(h + (size_t)t1i * DD + d0);

        float p0 = xi0.x * wAi.x + xi0.y * wAi.y + xi0.z * wAi.z + xi0.w * wAi.w
                 + xj0.x * wAj.x + xj0.y * wAj.y + xj0.z * wAj.z + xj0.w * wAj.w;
        float p1 = xi1.x * wAi.x + xi1.y * wAi.y + xi1.z * wAi.z + xi1.w * wAi.w
                 + xj1.x * wAj.x + xj1.y * wAj.y + xj1.z * wAj.z + xj1.w * wAj.w;
#pragma unroll
        for (int off = 16; off > 0; off >>= 1) {
            p0 += __shfl_xor_sync(0xffffffffu, p0, off);
            p1 += __shfl_xor_sync(0xffffffffu, p1, off);
        }
        const float a0 = 1.0f / (1.0f + __expf(-(p0 + ab)));
        const float a1 = 1.0f / (1.0f + __expf(-(p1 + ab)));

        const float4* ea0 = (const float4*)(edge_attr + (size_t)e0 * EDD);
        const float4* ea1 = (const float4*)(edge_attr + (size_t)e1 * EDD);
        float4 ev0 = eb, ev1 = eb;
#pragma unroll
        for (int q = 0; q < 4; q++) {
            const float4 u0 = __ldg(&ea0[q]);
            const float4 u1 = __ldg(&ea1[q]);
            ev0.x = fmaf(u0.x, wE[4*q+0].x, ev0.x); ev0.y = fmaf(u0.x, wE[4*q+0].y, ev0.y);
            ev0.z = fmaf(u0.x, wE[4*q+0].z, ev0.z); ev0.w = fmaf(u0.x, wE[4*q+0].w, ev0.w);
            ev0.x = fmaf(u0.y, wE[4*q+1].x, ev0.x); ev0.y = fmaf(u0.y, wE[4*q+1].y, ev0.y);
            ev0.z = fmaf(u0.y, wE[4*q+1].z, ev0.z); ev0.w = fmaf(u0.y, wE[4*q+1].w, ev0.w);
            ev0.x = fmaf(u0.z, wE[4*q+2].x, ev0.x); ev0.y = fmaf(u0.z, wE[4*q+2].y, ev0.y);
            ev0.z = fmaf(u0.z, wE[4*q+2].z, ev0.z); ev0.w = fmaf(u0.z, wE[4*q+2].w, ev0.w);
            ev0.x = fmaf(u0.w, wE[4*q+3].x, ev0.x); ev0.y = fmaf(u0.w, wE[4*q+3].y, ev0.y);
            ev0.z = fmaf(u0.w, wE[4*q+3].z, ev0.z); ev0.w = fmaf(u0.w, wE[4*q+3].w, ev0.w);

            ev1.x = fmaf(u1.x, wE[4*q+0].x, ev1.x); ev1.y = fmaf(u1.x, wE[4*q+0].y, ev1.y);
            ev1.z = fmaf(u1.x, wE[4*q+0].z, ev1.z); ev1.w = fmaf(u1.x, wE[4*q+0].w, ev1.w);
            ev1.x = fmaf(u1.y, wE[4*q+1].x, ev1.x); ev1.y = fmaf(u1.y, wE[4*q+1].y, ev1.y);
            ev1.z = fmaf(u1.y, wE[4*q+1].z, ev1.z); ev1.w = fmaf(u1.y, wE[4*q+1].w, ev1.w);
            ev1.x = fmaf(u1.z, wE[4*q+2].x, ev1.x); ev1.y = fmaf(u1.z, wE[4*q+2].y, ev1.y);
            ev1.z = fmaf(u1.z, wE[4*q+2].z, ev1.z); ev1.w = fmaf(u1.z, wE[4*q+2].w, ev1.w);
            ev1.x = fmaf(u1.w, wE[4*q+3].x, ev1.x); ev1.y = fmaf(u1.w, wE[4*q+3].y, ev1.y);
            ev1.z = fmaf(u1.w, wE[4*q+3].z, ev1.z); ev1.w = fmaf(u1.w, wE[4*q+3].w, ev1.w);
        }

        float4 m0, m1;
        m0.x = fmaxf(fmaf(xj0.x, a0, ev0.x), 0.0f);
        m0.y = fmaxf(fmaf(xj0.y, a0, ev0.y), 0.0f);
        m0.z = fmaxf(fmaf(xj0.z, a0, ev0.z), 0.0f);
        m0.w = fmaxf(fmaf(xj0.w, a0, ev0.w), 0.0f);
        m1.x = fmaxf(fmaf(xj1.x, a1, ev1.x), 0.0f);
        m1.y = fmaxf(fmaf(xj1.y, a1, ev1.y), 0.0f);
        m1.z = fmaxf(fmaf(xj1.z, a1, ev1.z), 0.0f);
        m1.w = fmaxf(fmaf(xj1.w, a1, ev1.w), 0.0f);

        float* dp0 = agg + (size_t)t0i * DD + d0;
        float* dp1 = agg + (size_t)t1i * DD + d0;
        asm volatile("red.global.add.v4.f32 [%0], {%1,%2,%3,%4};"
                     :: "l"(dp0), "f"(m0.x), "f"(m0.y), "f"(m0.z), "f"(m0.w) : "memory");
        asm volatile("red.global.add.v4.f32 [%0], {%1,%2,%3,%4};"
                     :: "l"(dp1), "f"(m1.x), "f"(m1.y), "f"(m1.z), "f"(m1.w) : "memory");
    }
}

// ---------------------------------------------------------------------------
// SGEMM v2: 128 threads, 128x128 tile, 16x8 per-thread, 3-stage cp.async(B)
// + register-staged transposed A. Epilogue: bias / BN(eval) / ReLU.
// ---------------------------------------------------------------------------
__global__ __launch_bounds__(128, 3)
void sgemm2_kernel(const float* __restrict__ A, const float* __restrict__ B,
                   const float* __restrict__ bias,
                   const float* __restrict__ bn_g, const float* __restrict__ bn_b,
                   float* __restrict__ C,
                   int M, int K, int Nc, int do_relu, int do_bn) {
    __shared__ float As[3][8][128];   // [stage][k][row]
    __shared__ float Bs[3][8][128];   // [stage][k][col]

    const int tid = threadIdx.x;
    const int tx = tid & 15;          // 16 col groups of 8
    const int ty = tid >> 4;          // 8 row groups of 16
    const int row0 = blockIdx.y * 128;
    const int col0 = blockIdx.x * 128;

    const int a_row = tid >> 1;           // 0..63
    const int a_col = (tid & 1) * 4;      // 0 or 4
    const int b_row = tid >> 4;           // 0..7
    const int b_col = (tid & 15) * 8;     // 0..120

    const int gr1 = row0 + a_row, gr2 = gr1 + 64;
    const bool v1 = gr1 < M, v2 = gr2 < M;
    const float* aptr1 = A + (size_t)gr1 * K + a_col;
    const float* aptr2 = A + (size_t)gr2 * K + a_col;
    const float* bptr  = B + (size_t)b_row * Nc + col0 + b_col;

    const int nt = K >> 3;
    const float4 f40 = make_float4(0.f, 0.f, 0.f, 0.f);
    float4 ar0, ar1;

#define LDG_A(k0) { ar0 = v1 ? *(const float4*)(aptr1 + (k0)) : f40; \
                    ar1 = v2 ? *(const float4*)(aptr2 + (k0)) : f40; }
#define STS_A(stg) { As[stg][a_col+0][a_row] = ar0.x; As[stg][a_col+1][a_row] = ar0.y; \
                     As[stg][a_col+2][a_row] = ar0.z; As[stg][a_col+3][a_row] = ar0.w; \
                     As[stg][a_col+0][a_row+64] = ar1.x; As[stg][a_col+1][a_row+64] = ar1.y; \
                     As[stg][a_col+2][a_row+64] = ar1.z; As[stg][a_col+3][a_row+64] = ar1.w; }
#define CP_B(stg, k0) { \
    uint32_t _d = (uint32_t)__cvta_generic_to_shared(&Bs[stg][b_row][b_col]); \
    const float* _s = bptr + (size_t)(k0) * Nc; \
    asm volatile("cp.async.cg.shared.global [%0], [%1], 16;\n\t" \
                 "cp.async.cg.shared.global [%2], [%3], 16;\n\t" \
                 "cp.async.commit_group;\n" \
                 :: "r"(_d), "l"(_s), "r"(_d + 16), "l"(_s + 4) : "memory"); }

    float acc[16][8];
#pragma unroll
    for (int i = 0; i < 16; i++)
#pragma unroll
        for (int j = 0; j < 8; j++) acc[i][j] = 0.0f;

    // Prologue: tiles 0 and 1
    LDG_A(0); CP_B(0, 0); STS_A(0);
    LDG_A(8); CP_B(1, 8);

    int st = 0, st1 = 1, st2 = 2;
#pragma unroll 1
    for (int t = 0; t < nt; t++) {
        if (t + 1 < nt) STS_A(st1);
        if (t + 2 < nt) { const int k0 = (t + 2) * 8; LDG_A(k0); CP_B(st2, k0); }
        const int rem = nt - 1 - t;
        if (rem >= 2)      asm volatile("cp.async.wait_group 2;" ::: "memory");
        else if (rem == 1) asm volatile("cp.async.wait_group 1;" ::: "memory");
        else               asm volatile("cp.async.wait_group 0;" ::: "memory");
        __syncthreads();

#pragma unroll
        for (int k = 0; k < 8; k++) {
            float4 pa0 = *(const float4*)&As[st][k][ty * 16];
            float4 pa1 = *(const float4*)&As[st][k][ty * 16 + 4];
            float4 pa2 = *(const float4*)&As[st][k][ty * 16 + 8];
            float4 pa3 = *(const float4*)&As[st][k][ty * 16 + 12];
            float4 pb0 = *(const float4*)&Bs[st][k][tx * 8];
            float4 pb1 = *(const float4*)&Bs[st][k][tx * 8 + 4];
            float af[16] = {pa0.x, pa0.y, pa0.z, pa0.w, pa1.x, pa1.y, pa1.z, pa1.w,
                            pa2.x, pa2.y, pa2.z, pa2.w, pa3.x, pa3.y, pa3.z, pa3.w};
            float bf[8]  = {pb0.x, pb0.y, pb0.z, pb0.w, pb1.x, pb1.y, pb1.z, pb1.w};
#pragma unroll
            for (int i = 0; i < 16; i++)
#pragma unroll
                for (int j = 0; j < 8; j++)
                    acc[i][j] = fmaf(af[i], bf[j], acc[i][j]);
        }
        const int tmp = st; st = st1; st1 = st2; st2 = tmp;
    }

    // Epilogue
    float bi[8], g[8], bb[8];
#pragma unroll
    for (int j = 0; j < 8; j++) {
        const int c = col0 + tx * 8 + j;
        bi[j] = bias[c];
        if (do_bn) { g[j] = bn_g[c]; bb[j] = bn_b[c]; }
    }
#pragma unroll
    for (int i = 0; i < 16; i++) {
        const int r = row0 + ty * 16 + i;
        if (r >= M) continue;
        float v[8];
#pragma unroll
        for (int j = 0; j < 8; j++) {
            float t = acc[i][j] + bi[j];
            if (do_bn) t = fmaf(g[j] * BN_INV, t, bb[j]);
            if (do_relu) t = fmaxf(t, 0.0f);
            v[j] = t;
        }
        float* cp = C + (size_t)r * Nc + col0 + tx * 8;
        *(float4*)cp       = make_float4(v[0], v[1], v[2], v[3]);
        *(float4*)(cp + 4) = make_float4(v[4], v[5], v[6], v[7]);
    }
#undef LDG_A
#undef STS_A
#undef CP_B
}

// ---------------------------------------------------------------------------
extern "C" void kernel_launch(void* const* d_in, const int* in_sizes, int n_in,
                              void* d_out, int out_size) {
    const float* x         = (const float*)d_in[0];
    const float* edge_attr = (const float*)d_in[1];
    const float* node_W    = (const float*)d_in[2];
    const float* node_b    = (const float*)d_in[3];
    const float* edge_W    = (const float*)d_in[4];
    const float* edge_b    = (const float*)d_in[5];
    const float* attn_W    = (const float*)d_in[6];
    const float* attn_b    = (const float*)d_in[7];
    const float* eps       = (const float*)d_in[8];
    const float* W1        = (const float*)d_in[9];
    const float* b1        = (const float*)d_in[10];
    const float* bn1_g     = (const float*)d_in[11];
    const float* bn1_b     = (const float*)d_in[12];
    const float* W2        = (const float*)d_in[13];
    const float* b2        = (const float*)d_in[14];
    const float* bn_g      = (const float*)d_in[15];
    const float* bn_b      = (const float*)d_in[16];
    const int*   edge_index= (const int*)d_in[17];

    float *hA, *hB, *agg, *tbuf;
    cudaGetSymbolAddress((void**)&hA,  g_h);
    cudaGetSymbolAddress((void**)&hB,  g_h2);
    cudaGetSymbolAddress((void**)&agg, g_agg);
    cudaGetSymbolAddress((void**)&tbuf, g_t);

    const int mblk = (NN + 127) / 128;     // 313
    const int n4 = NN * DD / 4;

    // node encoder: h = x @ node_W + node_b
    sgemm2_kernel<<<dim3(1, mblk), 128>>>(x, node_W, node_b, nullptr, nullptr,
                                          hA, NN, DD, DD, 0, 0);

    const float* hcur = hA;
    float* hnext = hB;
    for (int l = 0; l < LL; l++) {
        init_agg_kernel<<<(n4 + 255) / 256, 256>>>(hcur, eps + l, agg, n4);
        edge_kernel<<<2048, 128>>>(hcur, edge_attr, edge_index,
                                   edge_W + (size_t)l * EDD * DD,
                                   edge_b + (size_t)l * DD,
                                   attn_W + (size_t)l * 2 * DD,
                                   attn_b + l, agg);
        // t = relu(bn1(agg @ W1 + b1))   [N,128]@[128,256]
        sgemm2_kernel<<<dim3(2, mblk), 128>>>(agg, W1 + (size_t)l * DD * 2 * DD,
                                              b1 + (size_t)l * 2 * DD,
                                              bn1_g + (size_t)l * 2 * DD,
                                              bn1_b + (size_t)l * 2 * DD,
                                              tbuf, NN, DD, 2 * DD, 1, 1);
        // h' = [relu] bn(t @ W2 + b2)    [N,256]@[256,128]
        float* outp = (l == LL - 1) ? (float*)d_out : hnext;
        sgemm2_kernel<<<dim3(1, mblk), 128>>>(tbuf, W2 + (size_t)l * 2 * DD * DD,
                                              b2 + (size_t)l * DD,
                                              bn_g + (size_t)l * DD,
                                              bn_b + (size_t)l * DD,
                                              outp, NN, 2 * DD, DD, (l < LL - 1) ? 1 : 0, 1);
        if (l < LL - 1) {
            hcur = outp;
            hnext = (outp == hA) ? hB : hA;
        }
    }
}

// round 6
// speedup vs baseline: 1.9892x; 1.1266x over previous
#include <cuda_runtime.h>
#include <cstdint>

// Problem constants
#define NN 40000
#define EE 640000
#define DD 128
#define EDD 16
#define LL 3
#define BN_INV 0.99999500003749978f  // 1/sqrt(1+1e-5)

// Scratch (no cudaMalloc allowed)
__device__ float  g_h[(size_t)NN * DD];
__device__ float  g_h2[(size_t)NN * DD];
__device__ float  g_agg[(size_t)NN * DD];
__device__ float  g_t[(size_t)NN * 2 * DD];
__device__ float2 g_pre[NN];

// ---- f32x2 helpers --------------------------------------------------------
__device__ __forceinline__ unsigned long long pack2(float lo, float hi) {
    unsigned long long r;
    asm("mov.b64 %0, {%1, %2};" : "=l"(r) : "f"(lo), "f"(hi));
    return r;
}
__device__ __forceinline__ unsigned long long splat2(float x) {
    unsigned long long r;
    asm("mov.b64 %0, {%1, %1};" : "=l"(r) : "f"(x));
    return r;
}
__device__ __forceinline__ void ffma2(unsigned long long& d,
                                      unsigned long long a,
                                      unsigned long long b) {
    asm("fma.rn.f32x2 %0, %1, %2, %0;" : "+l"(d) : "l"(a), "l"(b));
}
__device__ __forceinline__ void unpack2(unsigned long long v, float& lo, float& hi) {
    asm("mov.b64 {%0, %1}, %2;" : "=f"(lo), "=f"(hi) : "l"(v));
}
__device__ __forceinline__ float fold2(unsigned long long v) {
    float lo, hi; unpack2(v, lo, hi); return lo + hi;
}

// ---------------------------------------------------------------------------
// prep: agg = (1+eps)*h  AND  pre[n] = (h[n]·attn_W[0:128], h[n]·attn_W[128:256])
// One warp per node.
// ---------------------------------------------------------------------------
__global__ __launch_bounds__(128)
void prep_kernel(const float* __restrict__ h,
                 const float* __restrict__ eps_l,
                 const float* __restrict__ attn_W,   // [256]
                 float* __restrict__ agg,
                 float2* __restrict__ pre) {
    const int warp = (blockIdx.x * blockDim.x + threadIdx.x) >> 5;
    const int lane = threadIdx.x & 31;
    if (warp >= NN) return;
    const int d0 = lane * 4;
    const float4 hv = *(const float4*)(h + (size_t)warp * DD + d0);
    const float s = 1.0f + eps_l[0];
    float4 o; o.x = hv.x * s; o.y = hv.y * s; o.z = hv.z * s; o.w = hv.w * s;
    *(float4*)(agg + (size_t)warp * DD + d0) = o;
    const float4 wi = *(const float4*)(attn_W + d0);
    const float4 wj = *(const float4*)(attn_W + DD + d0);
    float pi = hv.x * wi.x + hv.y * wi.y + hv.z * wi.z + hv.w * wi.w;
    float pj = hv.x * wj.x + hv.y * wj.y + hv.z * wj.z + hv.w * wj.w;
#pragma unroll
    for (int off = 16; off > 0; off >>= 1) {
        pi += __shfl_xor_sync(0xffffffffu, pi, off);
        pj += __shfl_xor_sync(0xffffffffu, pj, off);
    }
    if (lane == 0) pre[warp] = make_float2(pi, pj);
}

// ---------------------------------------------------------------------------
// Fused edge kernel v3: 2 edges/warp-iter, attention via precomputed dots,
// edge embedding via fma.rn.f32x2 with k-paired partial sums.
// ---------------------------------------------------------------------------
__global__ __launch_bounds__(128, 3)
void edge_kernel(const float* __restrict__ h,
                 const float* __restrict__ edge_attr,
                 const int* __restrict__ edge_index,
                 const float* __restrict__ edge_W,   // [16,128]
                 const float* __restrict__ edge_b,   // [128]
                 const float2* __restrict__ pre,     // [N]
                 const float* __restrict__ attn_b,   // [1]
                 float* __restrict__ agg) {
    const int lane = threadIdx.x & 31;
    const int gw = (blockIdx.x * blockDim.x + threadIdx.x) >> 5;
    const int nwarp = (gridDim.x * blockDim.x) >> 5;
    const int d0 = lane * 4;

    // Pack weights as (k even, k odd) pairs per output dim: wE2[k2*4+d]
    unsigned long long wE2[32];
#pragma unroll
    for (int k2 = 0; k2 < 8; k2++) {
        const float4 wa = *(const float4*)(edge_W + (2 * k2) * DD + d0);
        const float4 wb = *(const float4*)(edge_W + (2 * k2 + 1) * DD + d0);
        wE2[k2 * 4 + 0] = pack2(wa.x, wb.x);
        wE2[k2 * 4 + 1] = pack2(wa.y, wb.y);
        wE2[k2 * 4 + 2] = pack2(wa.z, wb.z);
        wE2[k2 * 4 + 3] = pack2(wa.w, wb.w);
    }
    unsigned long long ebp[4];
    {
        const float4 eb = *(const float4*)(edge_b + d0);
        ebp[0] = pack2(eb.x, 0.0f); ebp[1] = pack2(eb.y, 0.0f);
        ebp[2] = pack2(eb.z, 0.0f); ebp[3] = pack2(eb.w, 0.0f);
    }
    const float ab = attn_b[0];

    const int* __restrict__ src_arr = edge_index;
    const int* __restrict__ dst_arr = edge_index + EE;

#pragma unroll 1
    for (int e0 = gw * 2; e0 < EE; e0 += nwarp * 2) {
        const int e1 = e0 + 1;   // EE even -> always valid
        const int s0 = src_arr[e0], s1 = src_arr[e1];
        const int t0 = dst_arr[e0], t1 = dst_arr[e1];

        const float4 xj0 = *(const float4*)(h + (size_t)s0 * DD + d0);
        const float4 xj1 = *(const float4*)(h + (size_t)s1 * DD + d0);
        const float2 ps0 = __ldg(pre + s0), pd0 = __ldg(pre + t0);
        const float2 ps1 = __ldg(pre + s1), pd1 = __ldg(pre + t1);

        // edge_attr rows as packed f32 pairs (64B each, 16B aligned)
        const ulonglong2* ea0 = (const ulonglong2*)(edge_attr + (size_t)e0 * EDD);
        const ulonglong2* ea1 = (const ulonglong2*)(edge_attr + (size_t)e1 * EDD);
        const ulonglong2 q00 = __ldg(ea0 + 0), q01 = __ldg(ea0 + 1),
                         q02 = __ldg(ea0 + 2), q03 = __ldg(ea0 + 3);
        const ulonglong2 q10 = __ldg(ea1 + 0), q11 = __ldg(ea1 + 1),
                         q12 = __ldg(ea1 + 2), q13 = __ldg(ea1 + 3);

        const float a0 = 1.0f / (1.0f + __expf(-(pd0.x + ps0.y + ab)));
        const float a1 = 1.0f / (1.0f + __expf(-(pd1.x + ps1.y + ab)));

        // edge 0 embedding
        float e0v[4];
        {
            const unsigned long long ep[8] = {q00.x, q00.y, q01.x, q01.y,
                                              q02.x, q02.y, q03.x, q03.y};
            unsigned long long acc[4] = {ebp[0], ebp[1], ebp[2], ebp[3]};
#pragma unroll
            for (int k2 = 0; k2 < 8; k2++) {
                ffma2(acc[0], ep[k2], wE2[k2 * 4 + 0]);
                ffma2(acc[1], ep[k2], wE2[k2 * 4 + 1]);
                ffma2(acc[2], ep[k2], wE2[k2 * 4 + 2]);
                ffma2(acc[3], ep[k2], wE2[k2 * 4 + 3]);
            }
            e0v[0] = fold2(acc[0]); e0v[1] = fold2(acc[1]);
            e0v[2] = fold2(acc[2]); e0v[3] = fold2(acc[3]);
        }
        // edge 1 embedding
        float e1v[4];
        {
            const unsigned long long ep[8] = {q10.x, q10.y, q11.x, q11.y,
                                              q12.x, q12.y, q13.x, q13.y};
            unsigned long long acc[4] = {ebp[0], ebp[1], ebp[2], ebp[3]};
#pragma unroll
            for (int k2 = 0; k2 < 8; k2++) {
                ffma2(acc[0], ep[k2], wE2[k2 * 4 + 0]);
                ffma2(acc[1], ep[k2], wE2[k2 * 4 + 1]);
                ffma2(acc[2], ep[k2], wE2[k2 * 4 + 2]);
                ffma2(acc[3], ep[k2], wE2[k2 * 4 + 3]);
            }
            e1v[0] = fold2(acc[0]); e1v[1] = fold2(acc[1]);
            e1v[2] = fold2(acc[2]); e1v[3] = fold2(acc[3]);
        }

        float4 m0, m1;
        m0.x = fmaxf(fmaf(xj0.x, a0, e0v[0]), 0.0f);
        m0.y = fmaxf(fmaf(xj0.y, a0, e0v[1]), 0.0f);
        m0.z = fmaxf(fmaf(xj0.z, a0, e0v[2]), 0.0f);
        m0.w = fmaxf(fmaf(xj0.w, a0, e0v[3]), 0.0f);
        m1.x = fmaxf(fmaf(xj1.x, a1, e1v[0]), 0.0f);
        m1.y = fmaxf(fmaf(xj1.y, a1, e1v[1]), 0.0f);
        m1.z = fmaxf(fmaf(xj1.z, a1, e1v[2]), 0.0f);
        m1.w = fmaxf(fmaf(xj1.w, a1, e1v[3]), 0.0f);

        float* dp0 = agg + (size_t)t0 * DD + d0;
        float* dp1 = agg + (size_t)t1 * DD + d0;
        asm volatile("red.global.add.v4.f32 [%0], {%1,%2,%3,%4};"
                     :: "l"(dp0), "f"(m0.x), "f"(m0.y), "f"(m0.z), "f"(m0.w) : "memory");
        asm volatile("red.global.add.v4.f32 [%0], {%1,%2,%3,%4};"
                     :: "l"(dp1), "f"(m1.x), "f"(m1.y), "f"(m1.z), "f"(m1.w) : "memory");
    }
}

// ---------------------------------------------------------------------------
// SGEMM v3: 128 threads, 128x128 tile, 16x8 per-thread, FFMA2 core,
// 4-stage cp.async(B) pipeline (race-free) + register-staged transposed A.
// ---------------------------------------------------------------------------
__global__ __launch_bounds__(128, 3)
void sgemm3_kernel(const float* __restrict__ A, const float* __restrict__ B,
                   const float* __restrict__ bias,
                   const float* __restrict__ bn_g, const float* __restrict__ bn_b,
                   float* __restrict__ C,
                   int M, int K, int Nc, int do_relu, int do_bn) {
    __shared__ float As[4][8][128];   // [stage][k][row]
    __shared__ float Bs[4][8][128];   // [stage][k][col]

    const int tid = threadIdx.x;
    const int tx = tid & 15;          // 16 col groups of 8
    const int ty = tid >> 4;          // 8 row groups of 16
    const int row0 = blockIdx.y * 128;
    const int col0 = blockIdx.x * 128;

    const int a_row = tid >> 1;           // 0..63
    const int a_col = (tid & 1) * 4;      // 0 or 4
    const int b_row = tid >> 4;           // 0..7
    const int b_col = (tid & 15) * 8;     // 0..120

    const int gr1 = row0 + a_row, gr2 = gr1 + 64;
    const bool v1 = gr1 < M, v2 = gr2 < M;
    const float* aptr1 = A + (size_t)gr1 * K + a_col;
    const float* aptr2 = A + (size_t)gr2 * K + a_col;
    const float* bptr  = B + (size_t)b_row * Nc + col0 + b_col;

    const int nt = K >> 3;
    const float4 f40 = make_float4(0.f, 0.f, 0.f, 0.f);
    float4 ar0, ar1;

#define LDG_A(k0) { ar0 = v1 ? *(const float4*)(aptr1 + (k0)) : f40; \
                    ar1 = v2 ? *(const float4*)(aptr2 + (k0)) : f40; }
#define STS_A(stg) { As[stg][a_col+0][a_row] = ar0.x; As[stg][a_col+1][a_row] = ar0.y; \
                     As[stg][a_col+2][a_row] = ar0.z; As[stg][a_col+3][a_row] = ar0.w; \
                     As[stg][a_col+0][a_row+64] = ar1.x; As[stg][a_col+1][a_row+64] = ar1.y; \
                     As[stg][a_col+2][a_row+64] = ar1.z; As[stg][a_col+3][a_row+64] = ar1.w; }
#define CP_B(stg, k0) { \
    uint32_t _d = (uint32_t)__cvta_generic_to_shared(&Bs[stg][b_row][b_col]); \
    const float* _s = bptr + (size_t)(k0) * Nc; \
    asm volatile("cp.async.cg.shared.global [%0], [%1], 16;\n\t" \
                 "cp.async.cg.shared.global [%2], [%3], 16;\n\t" \
                 "cp.async.commit_group;\n" \
                 :: "r"(_d), "l"(_s), "r"(_d + 16), "l"(_s + 4) : "memory"); }

    unsigned long long acc2[8][8];   // [row-pair][col], lo=even row, hi=odd row
#pragma unroll
    for (int i = 0; i < 8; i++)
#pragma unroll
        for (int j = 0; j < 8; j++) acc2[i][j] = 0ull;

    // Prologue: tiles 0 and 1
    LDG_A(0); CP_B(0, 0); STS_A(0);
    LDG_A(8); CP_B(1, 8);

#pragma unroll 1
    for (int t = 0; t < nt; t++) {
        const int st = t & 3;
        if (t + 1 < nt) STS_A((t + 1) & 3);                 // regs hold tile t+1
        if (t + 2 < nt) { const int k0 = (t + 2) * 8; LDG_A(k0); CP_B((t + 2) & 3, k0); }
        const int rem = nt - 1 - t;
        if (rem >= 2)      asm volatile("cp.async.wait_group 2;" ::: "memory");
        else if (rem == 1) asm volatile("cp.async.wait_group 1;" ::: "memory");
        else               asm volatile("cp.async.wait_group 0;" ::: "memory");
        __syncthreads();

#pragma unroll
        for (int k = 0; k < 8; k++) {
            const ulonglong2 A0 = *(const ulonglong2*)&As[st][k][ty * 16];
            const ulonglong2 A1 = *(const ulonglong2*)&As[st][k][ty * 16 + 4];
            const ulonglong2 A2 = *(const ulonglong2*)&As[st][k][ty * 16 + 8];
            const ulonglong2 A3 = *(const ulonglong2*)&As[st][k][ty * 16 + 12];
            const unsigned long long ap[8] = {A0.x, A0.y, A1.x, A1.y,
                                              A2.x, A2.y, A3.x, A3.y};
            const float4 pb0 = *(const float4*)&Bs[st][k][tx * 8];
            const float4 pb1 = *(const float4*)&Bs[st][k][tx * 8 + 4];
            const float bf[8] = {pb0.x, pb0.y, pb0.z, pb0.w,
                                 pb1.x, pb1.y, pb1.z, pb1.w};
#pragma unroll
            for (int j = 0; j < 8; j++) {
                const unsigned long long bs = splat2(bf[j]);
#pragma unroll
                for (int ip = 0; ip < 8; ip++)
                    ffma2(acc2[ip][j], ap[ip], bs);
            }
        }
        __syncthreads();   // protect As[st]/Bs[st] from next iterations' writes
    }

    // Epilogue
    float bi[8], g[8], bb[8];
#pragma unroll
    for (int j = 0; j < 8; j++) {
        const int c = col0 + tx * 8 + j;
        bi[j] = bias[c];
        if (do_bn) { g[j] = bn_g[c]; bb[j] = bn_b[c]; }
    }
#pragma unroll
    for (int ip = 0; ip < 8; ip++) {
        const int r_lo = row0 + ty * 16 + 2 * ip;
        const int r_hi = r_lo + 1;
        float vlo[8], vhi[8];
#pragma unroll
        for (int j = 0; j < 8; j++) {
            float lo, hi; unpack2(acc2[ip][j], lo, hi);
            lo += bi[j]; hi += bi[j];
            if (do_bn) { lo = fmaf(g[j] * BN_INV, lo, bb[j]);
                         hi = fmaf(g[j] * BN_INV, hi, bb[j]); }
            if (do_relu) { lo = fmaxf(lo, 0.0f); hi = fmaxf(hi, 0.0f); }
            vlo[j] = lo; vhi[j] = hi;
        }
        if (r_lo < M) {
            float* cp = C + (size_t)r_lo * Nc + col0 + tx * 8;
            *(float4*)cp       = make_float4(vlo[0], vlo[1], vlo[2], vlo[3]);
            *(float4*)(cp + 4) = make_float4(vlo[4], vlo[5], vlo[6], vlo[7]);
        }
        if (r_hi < M) {
            float* cp = C + (size_t)r_hi * Nc + col0 + tx * 8;
            *(float4*)cp       = make_float4(vhi[0], vhi[1], vhi[2], vhi[3]);
            *(float4*)(cp + 4) = make_float4(vhi[4], vhi[5], vhi[6], vhi[7]);
        }
    }
#undef LDG_A
#undef STS_A
#undef CP_B
}

// ---------------------------------------------------------------------------
extern "C" void kernel_launch(void* const* d_in, const int* in_sizes, int n_in,
                              void* d_out, int out_size) {
    const float* x         = (const float*)d_in[0];
    const float* edge_attr = (const float*)d_in[1];
    const float* node_W    = (const float*)d_in[2];
    const float* node_b    = (const float*)d_in[3];
    const float* edge_W    = (const float*)d_in[4];
    const float* edge_b    = (const float*)d_in[5];
    const float* attn_W    = (const float*)d_in[6];
    const float* attn_b    = (const float*)d_in[7];
    const float* eps       = (const float*)d_in[8];
    const float* W1        = (const float*)d_in[9];
    const float* b1        = (const float*)d_in[10];
    const float* bn1_g     = (const float*)d_in[11];
    const float* bn1_b     = (const float*)d_in[12];
    const float* W2        = (const float*)d_in[13];
    const float* b2        = (const float*)d_in[14];
    const float* bn_g      = (const float*)d_in[15];
    const float* bn_b      = (const float*)d_in[16];
    const int*   edge_index= (const int*)d_in[17];

    float *hA, *hB, *agg, *tbuf; float2* pre;
    cudaGetSymbolAddress((void**)&hA,  g_h);
    cudaGetSymbolAddress((void**)&hB,  g_h2);
    cudaGetSymbolAddress((void**)&agg, g_agg);
    cudaGetSymbolAddress((void**)&tbuf, g_t);
    cudaGetSymbolAddress((void**)&pre, g_pre);

    const int mblk = (NN + 127) / 128;     // 313

    // node encoder: h = x @ node_W + node_b
    sgemm3_kernel<<<dim3(1, mblk), 128>>>(x, node_W, node_b, nullptr, nullptr,
                                          hA, NN, DD, DD, 0, 0);

    const float* hcur = hA;
    float* hnext = hB;
    for (int l = 0; l < LL; l++) {
        prep_kernel<<<10000, 128>>>(hcur, eps + l, attn_W + (size_t)l * 2 * DD,
                                    agg, pre);
        edge_kernel<<<2048, 128>>>(hcur, edge_attr, edge_index,
                                   edge_W + (size_t)l * EDD * DD,
                                   edge_b + (size_t)l * DD,
                                   pre, attn_b + l, agg);
        // t = relu(bn1(agg @ W1 + b1))   [N,128]@[128,256]
        sgemm3_kernel<<<dim3(2, mblk), 128>>>(agg, W1 + (size_t)l * DD * 2 * DD,
                                              b1 + (size_t)l * 2 * DD,
                                              bn1_g + (size_t)l * 2 * DD,
                                              bn1_b + (size_t)l * 2 * DD,
                                              tbuf, NN, DD, 2 * DD, 1, 1);
        // h' = [relu] bn(t @ W2 + b2)    [N,256]@[256,128]
        float* outp = (l == LL - 1) ? (float*)d_out : hnext;
        sgemm3_kernel<<<dim3(1, mblk), 128>>>(tbuf, W2 + (size_t)l * 2 * DD * DD,
                                              b2 + (size_t)l * DD,
                                              bn_g + (size_t)l * DD,
                                              bn_b + (size_t)l * DD,
                                              outp, NN, 2 * DD, DD, (l < LL - 1) ? 1 : 0, 1);
        if (l < LL - 1) {
            hcur = outp;
            hnext = (outp == hA) ? hB : hA;
        }
    }
}

// round 7
// speedup vs baseline: 2.1451x; 1.0784x over previous
#include <cuda_runtime.h>
#include <cstdint>

// Problem constants
#define NN 40000
#define EE 640000
#define DD 128
#define EDD 16
#define LL 3
#define BN_INV 0.99999500003749978f  // 1/sqrt(1+1e-5)

// Scratch (no cudaMalloc allowed)
__device__ float  g_h[(size_t)NN * DD];
__device__ float  g_h2[(size_t)NN * DD];
__device__ float  g_agg[(size_t)NN * DD];
__device__ float  g_t[(size_t)NN * 2 * DD];
__device__ float2 g_pre[NN];
__device__ int    g_deg[NN];
__device__ int    g_off[NN + 1];
__device__ int    g_cur[NN];
__device__ int    g_esrc[EE];   // src node id per CSR slot
__device__ int    g_eidx[EE];   // original edge id per CSR slot

// ---- f32x2 helpers --------------------------------------------------------
__device__ __forceinline__ unsigned long long pack2(float lo, float hi) {
    unsigned long long r;
    asm("mov.b64 %0, {%1, %2};" : "=l"(r) : "f"(lo), "f"(hi));
    return r;
}
__device__ __forceinline__ void ffma2(unsigned long long& d,
                                      unsigned long long a,
                                      unsigned long long b) {
    asm("fma.rn.f32x2 %0, %1, %2, %0;" : "+l"(d) : "l"(a), "l"(b));
}
__device__ __forceinline__ void unpack2(unsigned long long v, float& lo, float& hi) {
    asm("mov.b64 {%0, %1}, %2;" : "=f"(lo), "=f"(hi) : "l"(v));
}
__device__ __forceinline__ float fold2(unsigned long long v) {
    float lo, hi; unpack2(v, lo, hi); return lo + hi;
}

// ---------------------------------------------------------------------------
// CSR build (once per call): zero -> count -> scan -> fill
// ---------------------------------------------------------------------------
__global__ void zero_deg_kernel(int* __restrict__ deg) {
    int i = blockIdx.x * blockDim.x + threadIdx.x;
    if (i < NN) deg[i] = 0;
}

__global__ void count_kernel(const int* __restrict__ dst, int* __restrict__ deg) {
    int e = blockIdx.x * blockDim.x + threadIdx.x;
    if (e < EE) atomicAdd(&deg[dst[e]], 1);
}

__global__ __launch_bounds__(1024)
void scan_kernel(const int* __restrict__ deg, int* __restrict__ off,
                 int* __restrict__ cur) {
    __shared__ int part[1024];
    const int tid = threadIdx.x;
    const int per = (NN + 1023) / 1024;   // 40
    const int base = tid * per;
    int s = 0;
#pragma unroll 4
    for (int i = 0; i < per; i++) {
        const int n = base + i;
        if (n < NN) s += deg[n];
    }
    part[tid] = s;
    __syncthreads();
    for (int ofs = 1; ofs < 1024; ofs <<= 1) {
        int v = (tid >= ofs) ? part[tid - ofs] : 0;
        __syncthreads();
        part[tid] += v;
        __syncthreads();
    }
    int run = (tid > 0) ? part[tid - 1] : 0;   // exclusive prefix
    for (int i = 0; i < per; i++) {
        const int n = base + i;
        if (n < NN) {
            off[n] = run;
            cur[n] = run;
            run += deg[n];
        }
    }
    if (tid == 1023) off[NN] = EE;
}

__global__ void fill_kernel(const int* __restrict__ src,
                            const int* __restrict__ dst,
                            int* __restrict__ cur,
                            int* __restrict__ esrc,
                            int* __restrict__ eidx) {
    int e = blockIdx.x * blockDim.x + threadIdx.x;
    if (e >= EE) return;
    const int d = dst[e];
    const int p = atomicAdd(&cur[d], 1);
    esrc[p] = src[e];
    eidx[p] = e;
}

// ---------------------------------------------------------------------------
// prep: pre[n] = (h[n]·attn_W[0:128], h[n]·attn_W[128:256]). Warp per node.
// ---------------------------------------------------------------------------
__global__ __launch_bounds__(128)
void prep_kernel(const float* __restrict__ h,
                 const float* __restrict__ attn_W,   // [256]
                 float2* __restrict__ pre) {
    const int warp = (blockIdx.x * blockDim.x + threadIdx.x) >> 5;
    const int lane = threadIdx.x & 31;
    if (warp >= NN) return;
    const int d0 = lane * 4;
    const float4 hv = *(const float4*)(h + (size_t)warp * DD + d0);
    const float4 wi = *(const float4*)(attn_W + d0);
    const float4 wj = *(const float4*)(attn_W + DD + d0);
    float pi = hv.x * wi.x + hv.y * wi.y + hv.z * wi.z + hv.w * wi.w;
    float pj = hv.x * wj.x + hv.y * wj.y + hv.z * wj.z + hv.w * wj.w;
#pragma unroll
    for (int off = 16; off > 0; off >>= 1) {
        pi += __shfl_xor_sync(0xffffffffu, pi, off);
        pj += __shfl_xor_sync(0xffffffffu, pj, off);
    }
    if (lane == 0) pre[warp] = make_float2(pi, pj);
}

// ---------------------------------------------------------------------------
// CSR edge kernel: one warp per destination node. No atomics.
//   acc = (1+eps)*h[d] + sum_{e in in(d)} relu(h[src(e)]*a_e + ea_e @ W + b)
// ---------------------------------------------------------------------------
__global__ __launch_bounds__(128, 3)
void edge_csr_kernel(const float* __restrict__ h,
                     const float* __restrict__ edge_attr,
                     const int* __restrict__ off,
                     const int* __restrict__ esrc,
                     const int* __restrict__ eidx,
                     const float* __restrict__ edge_W,   // [16,128]
                     const float* __restrict__ edge_b,   // [128]
                     const float2* __restrict__ pre,     // [N]
                     const float* __restrict__ attn_b,   // [1]
                     const float* __restrict__ eps_l,
                     float* __restrict__ agg) {
    const int lane = threadIdx.x & 31;
    const int node = (blockIdx.x * blockDim.x + threadIdx.x) >> 5;
    if (node >= NN) return;
    const int d0 = lane * 4;

    // edge weights packed (k even, k odd) per output dim
    unsigned long long wE2[32];
#pragma unroll
    for (int k2 = 0; k2 < 8; k2++) {
        const float4 wa = *(const float4*)(edge_W + (2 * k2) * DD + d0);
        const float4 wb = *(const float4*)(edge_W + (2 * k2 + 1) * DD + d0);
        wE2[k2 * 4 + 0] = pack2(wa.x, wb.x);
        wE2[k2 * 4 + 1] = pack2(wa.y, wb.y);
        wE2[k2 * 4 + 2] = pack2(wa.z, wb.z);
        wE2[k2 * 4 + 3] = pack2(wa.w, wb.w);
    }
    unsigned long long ebp[4];
    {
        const float4 eb = *(const float4*)(edge_b + d0);
        ebp[0] = pack2(eb.x, 0.0f); ebp[1] = pack2(eb.y, 0.0f);
        ebp[2] = pack2(eb.z, 0.0f); ebp[3] = pack2(eb.w, 0.0f);
    }
    const float ab = attn_b[0];
    const int beg = off[node], end = off[node + 1];
    const float pd = __ldg(&pre[node].x) + ab;

    float4 acc;
    {
        const float s = 1.0f + eps_l[0];
        const float4 hv = *(const float4*)(h + (size_t)node * DD + d0);
        acc.x = hv.x * s; acc.y = hv.y * s; acc.z = hv.z * s; acc.w = hv.w * s;
    }

    int j = beg;
    for (; j + 2 <= end; j += 2) {
        const int s0 = esrc[j],     s1 = esrc[j + 1];
        const int i0 = eidx[j],     i1 = eidx[j + 1];
        const float4 xj0 = *(const float4*)(h + (size_t)s0 * DD + d0);
        const float4 xj1 = *(const float4*)(h + (size_t)s1 * DD + d0);
        const float pj0 = __ldg(&pre[s0].y);
        const float pj1 = __ldg(&pre[s1].y);
        const ulonglong2* ea0 = (const ulonglong2*)(edge_attr + (size_t)i0 * EDD);
        const ulonglong2* ea1 = (const ulonglong2*)(edge_attr + (size_t)i1 * EDD);
        const ulonglong2 q00 = __ldg(ea0 + 0), q01 = __ldg(ea0 + 1),
                         q02 = __ldg(ea0 + 2), q03 = __ldg(ea0 + 3);
        const ulonglong2 q10 = __ldg(ea1 + 0), q11 = __ldg(ea1 + 1),
                         q12 = __ldg(ea1 + 2), q13 = __ldg(ea1 + 3);
        const float a0 = 1.0f / (1.0f + __expf(-(pd + pj0)));
        const float a1 = 1.0f / (1.0f + __expf(-(pd + pj1)));

        const unsigned long long ep0[8] = {q00.x, q00.y, q01.x, q01.y,
                                           q02.x, q02.y, q03.x, q03.y};
        const unsigned long long ep1[8] = {q10.x, q10.y, q11.x, q11.y,
                                           q12.x, q12.y, q13.x, q13.y};
        unsigned long long a0v[4] = {ebp[0], ebp[1], ebp[2], ebp[3]};
        unsigned long long a1v[4] = {ebp[0], ebp[1], ebp[2], ebp[3]};
#pragma unroll
        for (int k2 = 0; k2 < 8; k2++) {
            ffma2(a0v[0], ep0[k2], wE2[k2 * 4 + 0]);
            ffma2(a0v[1], ep0[k2], wE2[k2 * 4 + 1]);
            ffma2(a0v[2], ep0[k2], wE2[k2 * 4 + 2]);
            ffma2(a0v[3], ep0[k2], wE2[k2 * 4 + 3]);
            ffma2(a1v[0], ep1[k2], wE2[k2 * 4 + 0]);
            ffma2(a1v[1], ep1[k2], wE2[k2 * 4 + 1]);
            ffma2(a1v[2], ep1[k2], wE2[k2 * 4 + 2]);
            ffma2(a1v[3], ep1[k2], wE2[k2 * 4 + 3]);
        }
        acc.x += fmaxf(fmaf(xj0.x, a0, fold2(a0v[0])), 0.0f)
               + fmaxf(fmaf(xj1.x, a1, fold2(a1v[0])), 0.0f);
        acc.y += fmaxf(fmaf(xj0.y, a0, fold2(a0v[1])), 0.0f)
               + fmaxf(fmaf(xj1.y, a1, fold2(a1v[1])), 0.0f);
        acc.z += fmaxf(fmaf(xj0.z, a0, fold2(a0v[2])), 0.0f)
               + fmaxf(fmaf(xj1.z, a1, fold2(a1v[2])), 0.0f);
        acc.w += fmaxf(fmaf(xj0.w, a0, fold2(a0v[3])), 0.0f)
               + fmaxf(fmaf(xj1.w, a1, fold2(a1v[3])), 0.0f);
    }
    if (j < end) {   // tail edge
        const int s0 = esrc[j];
        const int i0 = eidx[j];
        const float4 xj0 = *(const float4*)(h + (size_t)s0 * DD + d0);
        const float pj0 = __ldg(&pre[s0].y);
        const ulonglong2* ea0 = (const ulonglong2*)(edge_attr + (size_t)i0 * EDD);
        const ulonglong2 q00 = __ldg(ea0 + 0), q01 = __ldg(ea0 + 1),
                         q02 = __ldg(ea0 + 2), q03 = __ldg(ea0 + 3);
        const float a0 = 1.0f / (1.0f + __expf(-(pd + pj0)));
        const unsigned long long ep0[8] = {q00.x, q00.y, q01.x, q01.y,
                                           q02.x, q02.y, q03.x, q03.y};
        unsigned long long a0v[4] = {ebp[0], ebp[1], ebp[2], ebp[3]};
#pragma unroll
        for (int k2 = 0; k2 < 8; k2++) {
            ffma2(a0v[0], ep0[k2], wE2[k2 * 4 + 0]);
            ffma2(a0v[1], ep0[k2], wE2[k2 * 4 + 1]);
            ffma2(a0v[2], ep0[k2], wE2[k2 * 4 + 2]);
            ffma2(a0v[3], ep0[k2], wE2[k2 * 4 + 3]);
        }
        acc.x += fmaxf(fmaf(xj0.x, a0, fold2(a0v[0])), 0.0f);
        acc.y += fmaxf(fmaf(xj0.y, a0, fold2(a0v[1])), 0.0f);
        acc.z += fmaxf(fmaf(xj0.z, a0, fold2(a0v[2])), 0.0f);
        acc.w += fmaxf(fmaf(xj0.w, a0, fold2(a0v[3])), 0.0f);
    }

    *(float4*)(agg + (size_t)node * DD + d0) = acc;
}

// ---------------------------------------------------------------------------
// SGEMM: 128 threads, 128x128 tile, 16x8 per-thread, scalar FFMA core,
// 4-stage cp.async(B) pipeline, ONE barrier per k-tile (race-free at S=4).
// ---------------------------------------------------------------------------
__global__ __launch_bounds__(128, 3)
void sgemm_kernel(const float* __restrict__ A, const float* __restrict__ B,
                  const float* __restrict__ bias,
                  const float* __restrict__ bn_g, const float* __restrict__ bn_b,
                  float* __restrict__ C,
                  int M, int K, int Nc, int do_relu, int do_bn) {
    __shared__ float As[4][8][128];   // [stage][k][row]
    __shared__ float Bs[4][8][128];   // [stage][k][col]

    const int tid = threadIdx.x;
    const int tx = tid & 15;
    const int ty = tid >> 4;
    const int row0 = blockIdx.y * 128;
    const int col0 = blockIdx.x * 128;

    const int a_row = tid >> 1;
    const int a_col = (tid & 1) * 4;
    const int b_row = tid >> 4;
    const int b_col = (tid & 15) * 8;

    const int gr1 = row0 + a_row, gr2 = gr1 + 64;
    const bool v1 = gr1 < M, v2 = gr2 < M;
    const float* aptr1 = A + (size_t)gr1 * K + a_col;
    const float* aptr2 = A + (size_t)gr2 * K + a_col;
    const float* bptr  = B + (size_t)b_row * Nc + col0 + b_col;

    const int nt = K >> 3;
    const float4 f40 = make_float4(0.f, 0.f, 0.f, 0.f);
    float4 ar0, ar1;

#define LDG_A(k0) { ar0 = v1 ? *(const float4*)(aptr1 + (k0)) : f40; \
                    ar1 = v2 ? *(const float4*)(aptr2 + (k0)) : f40; }
#define STS_A(stg) { As[stg][a_col+0][a_row] = ar0.x; As[stg][a_col+1][a_row] = ar0.y; \
                     As[stg][a_col+2][a_row] = ar0.z; As[stg][a_col+3][a_row] = ar0.w; \
                     As[stg][a_col+0][a_row+64] = ar1.x; As[stg][a_col+1][a_row+64] = ar1.y; \
                     As[stg][a_col+2][a_row+64] = ar1.z; As[stg][a_col+3][a_row+64] = ar1.w; }
#define CP_B(stg, k0) { \
    uint32_t _d = (uint32_t)__cvta_generic_to_shared(&Bs[stg][b_row][b_col]); \
    const float* _s = bptr + (size_t)(k0) * Nc; \
    asm volatile("cp.async.cg.shared.global [%0], [%1], 16;\n\t" \
                 "cp.async.cg.shared.global [%2], [%3], 16;\n\t" \
                 "cp.async.commit_group;\n" \
                 :: "r"(_d), "l"(_s), "r"(_d + 16), "l"(_s + 4) : "memory"); }

    float acc[16][8];
#pragma unroll
    for (int i = 0; i < 16; i++)
#pragma unroll
        for (int j = 0; j < 8; j++) acc[i][j] = 0.0f;

    // Prologue: tiles 0 and 1
    LDG_A(0); CP_B(0, 0); STS_A(0);
    LDG_A(8); CP_B(1, 8);

#pragma unroll 1
    for (int t = 0; t < nt; t++) {
        const int st = t & 3;
        if (t + 1 < nt) STS_A((t + 1) & 3);
        if (t + 2 < nt) { const int k0 = (t + 2) * 8; LDG_A(k0); CP_B((t + 2) & 3, k0); }
        const int rem = nt - 1 - t;
        if (rem >= 2)      asm volatile("cp.async.wait_group 2;" ::: "memory");
        else if (rem == 1) asm volatile("cp.async.wait_group 1;" ::: "memory");
        else               asm volatile("cp.async.wait_group 0;" ::: "memory");
        __syncthreads();

#pragma unroll
        for (int k = 0; k < 8; k++) {
            float af[16], bf[8];
            *(float4*)&af[0]  = *(const float4*)&As[st][k][ty * 16];
            *(float4*)&af[4]  = *(const float4*)&As[st][k][ty * 16 + 4];
            *(float4*)&af[8]  = *(const float4*)&As[st][k][ty * 16 + 8];
            *(float4*)&af[12] = *(const float4*)&As[st][k][ty * 16 + 12];
            *(float4*)&bf[0]  = *(const float4*)&Bs[st][k][tx * 8];
            *(float4*)&bf[4]  = *(const float4*)&Bs[st][k][tx * 8 + 4];
#pragma unroll
            for (int i = 0; i < 16; i++)
#pragma unroll
                for (int j = 0; j < 8; j++)
                    acc[i][j] = fmaf(af[i], bf[j], acc[i][j]);
        }
    }

    // Epilogue
    float bi[8], g[8], bb[8];
#pragma unroll
    for (int j = 0; j < 8; j++) {
        const int c = col0 + tx * 8 + j;
        bi[j] = bias[c];
        if (do_bn) { g[j] = bn_g[c]; bb[j] = bn_b[c]; }
    }
#pragma unroll
    for (int i = 0; i < 16; i++) {
        const int r = row0 + ty * 16 + i;
        if (r >= M) continue;
        float v[8];
#pragma unroll
        for (int j = 0; j < 8; j++) {
            float t = acc[i][j] + bi[j];
            if (do_bn) t = fmaf(g[j] * BN_INV, t, bb[j]);
            if (do_relu) t = fmaxf(t, 0.0f);
            v[j] = t;
        }
        float* cp = C + (size_t)r * Nc + col0 + tx * 8;
        *(float4*)cp       = make_float4(v[0], v[1], v[2], v[3]);
        *(float4*)(cp + 4) = make_float4(v[4], v[5], v[6], v[7]);
    }
#undef LDG_A
#undef STS_A
#undef CP_B
}

// ---------------------------------------------------------------------------
extern "C" void kernel_launch(void* const* d_in, const int* in_sizes, int n_in,
                              void* d_out, int out_size) {
    const float* x         = (const float*)d_in[0];
    const float* edge_attr = (const float*)d_in[1];
    const float* node_W    = (const float*)d_in[2];
    const float* node_b    = (const float*)d_in[3];
    const float* edge_W    = (const float*)d_in[4];
    const float* edge_b    = (const float*)d_in[5];
    const float* attn_W    = (const float*)d_in[6];
    const float* attn_b    = (const float*)d_in[7];
    const float* eps       = (const float*)d_in[8];
    const float* W1        = (const float*)d_in[9];
    const float* b1        = (const float*)d_in[10];
    const float* bn1_g     = (const float*)d_in[11];
    const float* bn1_b     = (const float*)d_in[12];
    const float* W2        = (const float*)d_in[13];
    const float* b2        = (const float*)d_in[14];
    const float* bn_g      = (const float*)d_in[15];
    const float* bn_b      = (const float*)d_in[16];
    const int*   edge_index= (const int*)d_in[17];

    float *hA, *hB, *agg, *tbuf; float2* pre;
    int *deg, *off, *cur, *esrc, *eidx;
    cudaGetSymbolAddress((void**)&hA,   g_h);
    cudaGetSymbolAddress((void**)&hB,   g_h2);
    cudaGetSymbolAddress((void**)&agg,  g_agg);
    cudaGetSymbolAddress((void**)&tbuf, g_t);
    cudaGetSymbolAddress((void**)&pre,  g_pre);
    cudaGetSymbolAddress((void**)&deg,  g_deg);
    cudaGetSymbolAddress((void**)&off,  g_off);
    cudaGetSymbolAddress((void**)&cur,  g_cur);
    cudaGetSymbolAddress((void**)&esrc, g_esrc);
    cudaGetSymbolAddress((void**)&eidx, g_eidx);

    const int* src_arr = edge_index;
    const int* dst_arr = edge_index + EE;
    const int mblk = (NN + 127) / 128;     // 313

    // CSR build (overlaps node-encoder GEMM on the same stream order)
    zero_deg_kernel<<<(NN + 255) / 256, 256>>>(deg);
    count_kernel<<<(EE + 255) / 256, 256>>>(dst_arr, deg);
    scan_kernel<<<1, 1024>>>(deg, off, cur);
    fill_kernel<<<(EE + 255) / 256, 256>>>(src_arr, dst_arr, cur, esrc, eidx);

    // node encoder: h = x @ node_W + node_b
    sgemm_kernel<<<dim3(1, mblk), 128>>>(x, node_W, node_b, nullptr, nullptr,
                                         hA, NN, DD, DD, 0, 0);

    const float* hcur = hA;
    float* hnext = hB;
    for (int l = 0; l < LL; l++) {
        prep_kernel<<<10000, 128>>>(hcur, attn_W + (size_t)l * 2 * DD, pre);
        edge_csr_kernel<<<10000, 128>>>(hcur, edge_attr, off, esrc, eidx,
                                        edge_W + (size_t)l * EDD * DD,
                                        edge_b + (size_t)l * DD,
                                        pre, attn_b + l, eps + l, agg);
        // t = relu(bn1(agg @ W1 + b1))   [N,128]@[128,256]
        sgemm_kernel<<<dim3(2, mblk), 128>>>(agg, W1 + (size_t)l * DD * 2 * DD,
                                             b1 + (size_t)l * 2 * DD,
                                             bn1_g + (size_t)l * 2 * DD,
                                             bn1_b + (size_t)l * 2 * DD,
                                             tbuf, NN, DD, 2 * DD, 1, 1);
        // h' = [relu] bn(t @ W2 + b2)    [N,256]@[256,128]
        float* outp = (l == LL - 1) ? (float*)d_out : hnext;
        sgemm_kernel<<<dim3(1, mblk), 128>>>(tbuf, W2 + (size_t)l * 2 * DD * DD,
                                             b2 + (size_t)l * DD,
                                             bn_g + (size_t)l * DD,
                                             bn_b + (size_t)l * DD,
                                             outp, NN, 2 * DD, DD, (l < LL - 1) ? 1 : 0, 1);
        if (l < LL - 1) {
            hcur = outp;
            hnext = (outp == hA) ? hB : hA;
        }
    }
}